// round 12
// baseline (speedup 1.0000x reference)
#include <cuda_runtime.h>

// Problem constants (B=4, N=256, F=128)
#define B_  4
#define N_  256
#define F_  128
#define BN_ (B_*N_)
#define TJ  64
#define MS  68        // m1T row stride (floats): stores land conflict-free, 16B aligned
#define RB  2         // rows per CTA in pre_k / node_k (512 CTAs -> good occupancy)

// ---------------- device scratch (static: no allocation allowed) ----------------
__device__ float g_hln[BN_*F_];   // layernormed h
__device__ float g_xln[BN_*3];    // layernormed x
__device__ float g_Ae[BN_*F_];    // edg1_w[:, :F] @ h_ln + edg1_b
__device__ float g_Be[BN_*F_];    // edg1_w[:, F:2F] @ h_ln
__device__ float g_Ac[BN_*F_];    // cor1 analogues
__device__ float g_Bc[BN_*F_];
__device__ float g_agg[BN_*F_];   // sum_j e*m
__device__ float g_w2eT[F_*F_];   // edg2_w transposed (k-major)
__device__ float g_w2cT[F_*F_];   // cor2_w transposed
__device__ float g_n1wT[256*F_];  // node1_w transposed (k-major, k=0..255)
__device__ float g_n2wT[F_*F_];   // node2_w transposed
__device__ float g_e1T[256*F_];   // edg1_w[:, :2F] transposed
__device__ float g_c1T[256*F_];   // cor1_w[:, :2F] transposed

__device__ __forceinline__ float siluf(float z) {
    return __fdividef(z, 1.f + __expf(-z));
}

// ---- packed fp32x2 FMA (FFMA2; ptxas never emits it from C++) ----
__device__ __forceinline__ unsigned long long pack2(float x, float y) {
    unsigned long long r;
    asm("mov.b64 %0, {%1, %2};" : "=l"(r) : "f"(x), "f"(y));
    return r;
}
__device__ __forceinline__ void fma2(unsigned long long &d,
                                     unsigned long long a, unsigned long long b) {
    asm("fma.rn.f32x2 %0, %1, %2, %0;" : "+l"(d) : "l"(a), "l"(b));
}
__device__ __forceinline__ float2 unpack2(unsigned long long v) {
    float lo, hi;
    asm("mov.b64 {%0, %1}, %2;" : "=f"(lo), "=f"(hi) : "l"(v));
    return make_float2(lo, hi);
}

// ---------------- kernel: transpose weights to k-major ----------------
__global__ void transpose_k(const float* __restrict__ e2, const float* __restrict__ c2,
                            const float* __restrict__ n1, const float* __restrict__ n2,
                            const float* __restrict__ e1, const float* __restrict__ c1) {
    int k = blockIdx.x;   // 0..255
    int f = threadIdx.x;  // 0..127
    g_n1wT[k*F_ + f] = n1[f*256 + k];
    g_e1T [k*F_ + f] = e1[f*258 + k];
    g_c1T [k*F_ + f] = c1[f*258 + k];
    if (k < F_) {
        g_w2eT[k*F_ + f] = e2[f*F_ + k];
        g_w2cT[k*F_ + f] = c2[f*F_ + k];
        g_n2wT[k*F_ + f] = n2[f*F_ + k];
    }
}

// ---------------- kernel: per-node precompute, RB rows per CTA ----------------
__global__ void pre_k(const float* __restrict__ x,  const float* __restrict__ h,
                      const float* __restrict__ lnh_w, const float* __restrict__ lnh_b,
                      const float* __restrict__ lnx_w, const float* __restrict__ lnx_b,
                      const float* __restrict__ e1b, const float* __restrict__ c1b) {
    int row0 = blockIdx.x * RB;
    int f    = threadIdx.x;
    int lane = f & 31, wp = f >> 5;
    __shared__ float hln[RB][F_];
    __shared__ float red[RB][4];

    float v[RB], d[RB];
    #pragma unroll
    for (int r = 0; r < RB; r++) v[r] = h[(row0 + r)*F_ + f];
    #pragma unroll
    for (int r = 0; r < RB; r++) {
        float s = v[r];
        #pragma unroll
        for (int o = 16; o; o >>= 1) s += __shfl_xor_sync(0xffffffffu, s, o);
        if (lane == 0) red[r][wp] = s;
    }
    __syncthreads();
    #pragma unroll
    for (int r = 0; r < RB; r++) {
        float mean = (red[r][0] + red[r][1] + red[r][2] + red[r][3]) * (1.f / F_);
        d[r] = v[r] - mean;
    }
    __syncthreads();
    #pragma unroll
    for (int r = 0; r < RB; r++) {
        float s2 = d[r] * d[r];
        #pragma unroll
        for (int o = 16; o; o >>= 1) s2 += __shfl_xor_sync(0xffffffffu, s2, o);
        if (lane == 0) red[r][wp] = s2;
    }
    __syncthreads();
    float gw = lnh_w[f], gb = lnh_b[f];
    #pragma unroll
    for (int r = 0; r < RB; r++) {
        float var  = (red[r][0] + red[r][1] + red[r][2] + red[r][3]) * (1.f / F_);
        float hl = d[r] * rsqrtf(var + 1e-5f) * gw + gb;
        hln[r][f] = hl;
        g_hln[(row0 + r)*F_ + f] = hl;
    }

    if (f < RB) {  // layernorm of x (3 comps) for row f
        int row = row0 + f;
        float a0 = x[row*3+0], a1 = x[row*3+1], a2 = x[row*3+2];
        float m  = (a0 + a1 + a2) * (1.f/3.f);
        float d0 = a0 - m, d1 = a1 - m, d2 = a2 - m;
        float vr = (d0*d0 + d1*d1 + d2*d2) * (1.f/3.f);
        float rs = rsqrtf(vr + 1e-5f);
        g_xln[row*3+0] = d0*rs*lnx_w[0] + lnx_b[0];
        g_xln[row*3+1] = d1*rs*lnx_w[1] + lnx_b[1];
        g_xln[row*3+2] = d2*rs*lnx_w[2] + lnx_b[2];
    }
    __syncthreads();

    // A/B decomposition of layer-1
    float ae[RB], be[RB], ac[RB], bc[RB];
    float eb = e1b[f], cb = c1b[f];
    #pragma unroll
    for (int r = 0; r < RB; r++) { ae[r] = eb; be[r] = 0.f; ac[r] = cb; bc[r] = 0.f; }
    #pragma unroll 4
    for (int k = 0; k < F_; k++) {
        float ea = g_e1T[k*F_ + f];
        float eB = g_e1T[(128 + k)*F_ + f];
        float ca = g_c1T[k*F_ + f];
        float cB = g_c1T[(128 + k)*F_ + f];
        #pragma unroll
        for (int r = 0; r < RB; r++) {
            float hk = hln[r][k];
            ae[r] += ea*hk; be[r] += eB*hk; ac[r] += ca*hk; bc[r] += cB*hk;
        }
    }
    #pragma unroll
    for (int r = 0; r < RB; r++) {
        g_Ae[(row0+r)*F_+f] = ae[r]; g_Be[(row0+r)*F_+f] = be[r];
        g_Ac[(row0+r)*F_+f] = ac[r]; g_Bc[(row0+r)*F_+f] = bc[r];
    }
}

// ---------------- the pair kernel: one CTA per (b,i), 512 threads ----------------
// SMEM floats: w2e 16384 | w2c 16384 | m1eT 128*68 | m1cT 128*68 | dsq 256 | r0 256
//              shift 768 | xi 8 | aggred 8*128 | csum 8*4  = 52520 floats = 210080 B
#define PAIR_SMEM_BYTES (52520 * 4)

__global__ __launch_bounds__(512, 1)
void pair_k(const float* __restrict__ x,   const float* __restrict__ x0,
            const float* __restrict__ e1w, const float* __restrict__ c1w,
            const float* __restrict__ e2b, const float* __restrict__ c2b,
            const float* __restrict__ eiw, const float* __restrict__ eib,
            const float* __restrict__ c3w, const float* __restrict__ c3b,
            float* __restrict__ out_x) {
    extern __shared__ float sm[];
    float* w2e      = sm;                  // [128][128] k-major
    float* w2c      = w2e + F_*F_;
    float* m1eT     = w2c + F_*F_;         // [128 k][68] (j in columns)
    float* m1cT     = m1eT + F_*MS;
    float* dsq_sh   = m1cT + F_*MS;        // [N_]
    float* r0_sh    = dsq_sh + N_;         // [N_]
    float* shift_sh = r0_sh + N_;          // [N_][3]
    float* xi_sh    = shift_sh + N_*3;     // x_i (3) at [0..2], x0_i (3) at [4..6]
    float* aggred   = xi_sh + 8;           // [8][128]
    float* csum_sh  = aggred + 8*F_;       // [8][4]

    int tid  = threadIdx.x;
    int rowI = blockIdx.x;
    int b    = rowI >> 8;
    int i    = rowI & 255;

    // stage both transposed weight matrices into SMEM
    for (int idx = tid; idx < F_*F_/4; idx += 512) {
        ((float4*)w2e)[idx] = ((const float4*)g_w2eT)[idx];
        ((float4*)w2c)[idx] = ((const float4*)g_w2cT)[idx];
    }

    // ---- phase 0 (hoisted): all N_ per-j geometric scalars, once ----
    if (tid < N_) {
        int j = tid;
        float xi0 = x[rowI*3+0], xi1 = x[rowI*3+1], xi2 = x[rowI*3+2];
        const float* xj = x + (b*N_ + j)*3;
        float dx = xi0 - xj[0];
        float dy = xi1 - xj[1];
        float dz = xi2 - xj[2];
        float ds = dx*dx + dy*dy + dz*dz;
        float r  = sqrtf(ds);
        float ri = __fdividef(1.f, r + 1.f);
        dsq_sh[j] = ds;
        shift_sh[j*3+0] = dx * ri;
        shift_sh[j*3+1] = dy * ri;
        shift_sh[j*3+2] = dz * ri;
        float yi0 = x0[rowI*3+0], yi1 = x0[rowI*3+1], yi2 = x0[rowI*3+2];
        const float* x0j = x0 + (b*N_ + j)*3;
        float ex = yi0 - x0j[0];
        float ey = yi1 - x0j[1];
        float ez = yi2 - x0j[2];
        r0_sh[j] = sqrtf(ex*ex + ey*ey + ez*ez);
    }

    // phase-1 mapping: thread handles feature f1, j's congruent to jg (mod 4)
    int f1 = tid >> 2;
    int jg = tid & 3;
    float ae  = g_Ae[rowI*F_ + f1];
    float ac  = g_Ac[rowI*F_ + f1];
    float wed = e1w[f1*258 + 256], wer = e1w[f1*258 + 257];
    float wcd = c1w[f1*258 + 256], wcr = c1w[f1*258 + 257];

    // GEMM mapping: 16 warps; wg = role (0 edge, 1 cor); wj = j-octet; lane tf = f quad
    int w  = tid >> 5, tf = tid & 31;
    int wg = w >> 3, wj = w & 7;
    const float* w2  = wg ? w2c : w2e;
    const float* m1T = wg ? m1cT : m1eT;
    float4 b2   = ((const float4*)(wg ? c2b : e2b))[tf];
    float4 wout = ((const float4*)(wg ? c3w : eiw))[tf];
    float  bout = wg ? c3b[0] : eib[0];

    float4 aggr = make_float4(0.f, 0.f, 0.f, 0.f);   // edge warps only
    float  csum_acc = 0.f;                            // cor warps only

    // ---- preload tile-0 layer-1 inputs into registers ----
    float be_reg[16], bc_reg[16];
    #pragma unroll
    for (int u = 0; u < 16; u++) {
        int j = jg + u*4;
        be_reg[u] = g_Be[(b*N_ + j)*F_ + f1];
        bc_reg[u] = g_Bc[(b*N_ + j)*F_ + f1];
    }

    __syncthreads();

    for (int t = 0; t < N_/TJ; t++) {
        int j0 = t * TJ;

        // ---- phase 1: layer-1 (decomposed) + silu -> transposed m1 tiles ----
        #pragma unroll
        for (int u = 0; u < 16; u++) {
            int jj = jg + u*4;
            float ds = dsq_sh[j0 + jj], rr = r0_sh[j0 + jj];
            float ze = ae + be_reg[u] + wed*ds + wer*rr;
            float zc = ac + bc_reg[u] + wcd*ds + wcr*rr;
            m1eT[f1*MS + jj] = siluf(ze);
            m1cT[f1*MS + jj] = siluf(zc);
        }
        // ---- preload next tile's inputs (drains under the GEMM) ----
        if (t < N_/TJ - 1) {
            #pragma unroll
            for (int u = 0; u < 16; u++) {
                int j = j0 + TJ + jg + u*4;
                be_reg[u] = g_Be[(b*N_ + j)*F_ + f1];
                bc_reg[u] = g_Bc[(b*N_ + j)*F_ + f1];
            }
        }
        __syncthreads();

        // ---- phase 2: role-split GEMM (each warp: 8 j x 128 f, lane: 8 j x 4 f) ----
        {
            unsigned long long acc[4][4];   // [j-pair][f]
            #pragma unroll
            for (int p = 0; p < 4; p++) {
                acc[p][0] = pack2(b2.x, b2.x);
                acc[p][1] = pack2(b2.y, b2.y);
                acc[p][2] = pack2(b2.z, b2.z);
                acc[p][3] = pack2(b2.w, b2.w);
            }
            #pragma unroll 4
            for (int k = 0; k < F_; k++) {
                float4 w4 = *(const float4*)&w2[k*F_ + tf*4];
                ulonglong2 mA = *(const ulonglong2*)&m1T[k*MS + wj*8];      // (j0,j1),(j2,j3)
                ulonglong2 mB = *(const ulonglong2*)&m1T[k*MS + wj*8 + 4];  // (j4,j5),(j6,j7)
                unsigned long long ws;
                ws = pack2(w4.x, w4.x);
                fma2(acc[0][0], mA.x, ws); fma2(acc[1][0], mA.y, ws);
                fma2(acc[2][0], mB.x, ws); fma2(acc[3][0], mB.y, ws);
                ws = pack2(w4.y, w4.y);
                fma2(acc[0][1], mA.x, ws); fma2(acc[1][1], mA.y, ws);
                fma2(acc[2][1], mB.x, ws); fma2(acc[3][1], mB.y, ws);
                ws = pack2(w4.z, w4.z);
                fma2(acc[0][2], mA.x, ws); fma2(acc[1][2], mA.y, ws);
                fma2(acc[2][2], mB.x, ws); fma2(acc[3][2], mB.y, ws);
                ws = pack2(w4.w, w4.w);
                fma2(acc[0][3], mA.x, ws); fma2(acc[1][3], mA.y, ws);
                fma2(acc[2][3], mB.x, ws); fma2(acc[3][3], mB.y, ws);
            }
            // epilogue: per j, silu -> 1-wide head -> gate/accumulate
            #pragma unroll
            for (int p = 0; p < 4; p++) {
                float2 h0 = unpack2(acc[p][0]);
                float2 h1 = unpack2(acc[p][1]);
                float2 h2 = unpack2(acc[p][2]);
                float2 h3 = unpack2(acc[p][3]);
                #pragma unroll
                for (int q = 0; q < 2; q++) {
                    int jj = wj*8 + p*2 + q;
                    float m0 = siluf(q ? h0.y : h0.x);
                    float m1 = siluf(q ? h1.y : h1.x);
                    float m2 = siluf(q ? h2.y : h2.x);
                    float m3 = siluf(q ? h3.y : h3.x);
                    float pdot = m0*wout.x + m1*wout.y + m2*wout.z + m3*wout.w;
                    #pragma unroll
                    for (int o = 16; o; o >>= 1)
                        pdot += __shfl_xor_sync(0xffffffffu, pdot, o);
                    if (wg == 0) {
                        float e = __fdividef(1.f, 1.f + __expf(-(pdot + bout)));
                        if (j0 + jj == i) e = 0.f;          // (1 - eye) mask
                        aggr.x += e*m0; aggr.y += e*m1; aggr.z += e*m2; aggr.w += e*m3;
                    } else {
                        float cw = pdot + bout;              // no activation on cor3
                        float sv = (tf < 3) ? shift_sh[(j0 + jj)*3 + tf] : 0.f;
                        csum_acc += cw * sv;                 // diagonal: shift == 0 exactly
                    }
                }
            }
        }
        __syncthreads();   // protect m1 before next tile overwrites
    }

    // ---- final reductions across warps ----
    if (wg == 0) *((float4*)&aggred[wj*F_ + tf*4]) = aggr;
    else if (tf < 3) csum_sh[wj*4 + tf] = csum_acc;
    __syncthreads();
    if (tid < F_) {
        float s = 0.f;
        #pragma unroll
        for (int ww = 0; ww < 8; ww++) s += aggred[ww*F_ + tid];
        g_agg[rowI*F_ + tid] = s;
    }
    if (tid < 3) {
        float s = 0.f;
        #pragma unroll
        for (int ww = 0; ww < 8; ww++) s += csum_sh[ww*4 + tid];
        out_x[rowI*3 + tid] = g_xln[rowI*3 + tid] + s;
    }
}

// ---------------- kernel: node update, RB rows per CTA ----------------
__global__ void node_k(const float* __restrict__ n1b, const float* __restrict__ n2b,
                       float* __restrict__ out_h) {
    int row0 = blockIdx.x * RB;
    int f    = threadIdx.x;
    __shared__ float hln[RB][F_], agg[RB][F_], nu[RB][F_];
    #pragma unroll
    for (int r = 0; r < RB; r++) {
        hln[r][f] = g_hln[(row0+r)*F_ + f];
        agg[r][f] = g_agg[(row0+r)*F_ + f];
    }
    __syncthreads();
    float z[RB];
    float b1 = n1b[f];
    #pragma unroll
    for (int r = 0; r < RB; r++) z[r] = b1;
    #pragma unroll 4
    for (int k = 0; k < F_; k++) {
        float w1 = g_n1wT[k*F_ + f];
        float w2 = g_n1wT[(128 + k)*F_ + f];
        #pragma unroll
        for (int r = 0; r < RB; r++) z[r] += w1*hln[r][k] + w2*agg[r][k];
    }
    #pragma unroll
    for (int r = 0; r < RB; r++) nu[r][f] = siluf(z[r]);
    __syncthreads();
    float o[RB];
    float b2 = n2b[f];
    #pragma unroll
    for (int r = 0; r < RB; r++) o[r] = b2;
    #pragma unroll 4
    for (int k = 0; k < F_; k++) {
        float wv = g_n2wT[k*F_ + f];
        #pragma unroll
        for (int r = 0; r < RB; r++) o[r] += wv*nu[r][k];
    }
    #pragma unroll
    for (int r = 0; r < RB; r++) out_h[(row0+r)*F_ + f] = hln[r][f] + o[r];
}

// ---------------- launch ----------------
extern "C" void kernel_launch(void* const* d_in, const int* in_sizes, int n_in,
                              void* d_out, int out_size) {
    const float* x      = (const float*)d_in[0];
    const float* h      = (const float*)d_in[1];
    const float* x0     = (const float*)d_in[2];
    const float* lnh_w  = (const float*)d_in[3];
    const float* lnh_b  = (const float*)d_in[4];
    const float* lnx_w  = (const float*)d_in[5];
    const float* lnx_b  = (const float*)d_in[6];
    const float* edg1_w = (const float*)d_in[7];
    const float* edg1_b = (const float*)d_in[8];
    const float* edg2_w = (const float*)d_in[9];
    const float* edg2_b = (const float*)d_in[10];
    const float* edgi_w = (const float*)d_in[11];
    const float* edgi_b = (const float*)d_in[12];
    const float* node1_w = (const float*)d_in[13];
    const float* node1_b = (const float*)d_in[14];
    const float* node2_w = (const float*)d_in[15];
    const float* node2_b = (const float*)d_in[16];
    const float* cor1_w = (const float*)d_in[17];
    const float* cor1_b = (const float*)d_in[18];
    const float* cor2_w = (const float*)d_in[19];
    const float* cor2_b = (const float*)d_in[20];
    const float* cor3_w = (const float*)d_in[21];
    const float* cor3_b = (const float*)d_in[22];

    float* out   = (float*)d_out;
    float* out_x = out;                 // (B,N,3) first
    float* out_h = out + BN_*3;         // then (B,N,F)

    cudaFuncSetAttribute(pair_k, cudaFuncAttributeMaxDynamicSharedMemorySize,
                         PAIR_SMEM_BYTES);

    transpose_k<<<256, F_>>>(edg2_w, cor2_w, node1_w, node2_w, edg1_w, cor1_w);
    pre_k<<<BN_/RB, F_>>>(x, h, lnh_w, lnh_b, lnx_w, lnx_b, edg1_b, cor1_b);
    pair_k<<<BN_, 512, PAIR_SMEM_BYTES>>>(x, x0, edg1_w, cor1_w,
                                          edg2_b, cor2_b, edgi_w, edgi_b,
                                          cor3_w, cor3_b, out_x);
    node_k<<<BN_/RB, F_>>>(node1_b, node2_b, out_h);
}

// round 13
// speedup vs baseline: 1.0033x; 1.0033x over previous
#include <cuda_runtime.h>

// Problem constants (B=4, N=256, F=128)
#define B_  4
#define N_  256
#define F_  128
#define BN_ (B_*N_)
#define TJ  64
#define MS  68        // m1T row stride (floats): stores land conflict-free, 16B aligned
#define RB  2         // rows per CTA in pre_k / node_k (512 CTAs -> good occupancy)

// ---------------- device scratch (static: no allocation allowed) ----------------
__device__ float g_hln[BN_*F_];   // layernormed h
__device__ float g_xln[BN_*3];    // layernormed x
__device__ float g_Ae[BN_*F_];    // edg1_w[:, :F] @ h_ln + edg1_b
__device__ float g_Be[BN_*F_];    // edg1_w[:, F:2F] @ h_ln
__device__ float g_Ac[BN_*F_];    // cor1 analogues
__device__ float g_Bc[BN_*F_];
__device__ float g_agg[BN_*F_];   // sum_j e*m
__device__ float g_w2eT[F_*F_];   // edg2_w transposed (k-major)
__device__ float g_w2cT[F_*F_];   // cor2_w transposed
__device__ float g_n1wT[256*F_];  // node1_w transposed (k-major, k=0..255)
__device__ float g_n2wT[F_*F_];   // node2_w transposed
__device__ float g_e1T[256*F_];   // edg1_w[:, :2F] transposed
__device__ float g_c1T[256*F_];   // cor1_w[:, :2F] transposed

__device__ __forceinline__ float siluf(float z) {
    return __fdividef(z, 1.f + __expf(-z));
}

// ---- packed fp32x2 FMA (FFMA2; ptxas never emits it from C++) ----
__device__ __forceinline__ unsigned long long pack2(float x, float y) {
    unsigned long long r;
    asm("mov.b64 %0, {%1, %2};" : "=l"(r) : "f"(x), "f"(y));
    return r;
}
__device__ __forceinline__ void fma2(unsigned long long &d,
                                     unsigned long long a, unsigned long long b) {
    asm("fma.rn.f32x2 %0, %1, %2, %0;" : "+l"(d) : "l"(a), "l"(b));
}
__device__ __forceinline__ float2 unpack2(unsigned long long v) {
    float lo, hi;
    asm("mov.b64 {%0, %1}, %2;" : "=f"(lo), "=f"(hi) : "l"(v));
    return make_float2(lo, hi);
}

// ---------------- kernel: transpose weights to k-major ----------------
__global__ void transpose_k(const float* __restrict__ e2, const float* __restrict__ c2,
                            const float* __restrict__ n1, const float* __restrict__ n2,
                            const float* __restrict__ e1, const float* __restrict__ c1) {
    int k = blockIdx.x;   // 0..255
    int f = threadIdx.x;  // 0..127
    g_n1wT[k*F_ + f] = n1[f*256 + k];
    g_e1T [k*F_ + f] = e1[f*258 + k];
    g_c1T [k*F_ + f] = c1[f*258 + k];
    if (k < F_) {
        g_w2eT[k*F_ + f] = e2[f*F_ + k];
        g_w2cT[k*F_ + f] = c2[f*F_ + k];
        g_n2wT[k*F_ + f] = n2[f*F_ + k];
    }
}

// ---------------- kernel: per-node precompute, RB rows per CTA ----------------
__global__ void pre_k(const float* __restrict__ x,  const float* __restrict__ h,
                      const float* __restrict__ lnh_w, const float* __restrict__ lnh_b,
                      const float* __restrict__ lnx_w, const float* __restrict__ lnx_b,
                      const float* __restrict__ e1b, const float* __restrict__ c1b) {
    int row0 = blockIdx.x * RB;
    int f    = threadIdx.x;
    int lane = f & 31, wp = f >> 5;
    __shared__ float hln[RB][F_];
    __shared__ float red[RB][4];

    float v[RB], d[RB];
    #pragma unroll
    for (int r = 0; r < RB; r++) v[r] = h[(row0 + r)*F_ + f];
    #pragma unroll
    for (int r = 0; r < RB; r++) {
        float s = v[r];
        #pragma unroll
        for (int o = 16; o; o >>= 1) s += __shfl_xor_sync(0xffffffffu, s, o);
        if (lane == 0) red[r][wp] = s;
    }
    __syncthreads();
    #pragma unroll
    for (int r = 0; r < RB; r++) {
        float mean = (red[r][0] + red[r][1] + red[r][2] + red[r][3]) * (1.f / F_);
        d[r] = v[r] - mean;
    }
    __syncthreads();
    #pragma unroll
    for (int r = 0; r < RB; r++) {
        float s2 = d[r] * d[r];
        #pragma unroll
        for (int o = 16; o; o >>= 1) s2 += __shfl_xor_sync(0xffffffffu, s2, o);
        if (lane == 0) red[r][wp] = s2;
    }
    __syncthreads();
    float gw = lnh_w[f], gb = lnh_b[f];
    #pragma unroll
    for (int r = 0; r < RB; r++) {
        float var  = (red[r][0] + red[r][1] + red[r][2] + red[r][3]) * (1.f / F_);
        float hl = d[r] * rsqrtf(var + 1e-5f) * gw + gb;
        hln[r][f] = hl;
        g_hln[(row0 + r)*F_ + f] = hl;
    }

    if (f < RB) {  // layernorm of x (3 comps) for row f
        int row = row0 + f;
        float a0 = x[row*3+0], a1 = x[row*3+1], a2 = x[row*3+2];
        float m  = (a0 + a1 + a2) * (1.f/3.f);
        float d0 = a0 - m, d1 = a1 - m, d2 = a2 - m;
        float vr = (d0*d0 + d1*d1 + d2*d2) * (1.f/3.f);
        float rs = rsqrtf(vr + 1e-5f);
        g_xln[row*3+0] = d0*rs*lnx_w[0] + lnx_b[0];
        g_xln[row*3+1] = d1*rs*lnx_w[1] + lnx_b[1];
        g_xln[row*3+2] = d2*rs*lnx_w[2] + lnx_b[2];
    }
    __syncthreads();

    // A/B decomposition of layer-1
    float ae[RB], be[RB], ac[RB], bc[RB];
    float eb = e1b[f], cb = c1b[f];
    #pragma unroll
    for (int r = 0; r < RB; r++) { ae[r] = eb; be[r] = 0.f; ac[r] = cb; bc[r] = 0.f; }
    #pragma unroll 4
    for (int k = 0; k < F_; k++) {
        float ea = g_e1T[k*F_ + f];
        float eB = g_e1T[(128 + k)*F_ + f];
        float ca = g_c1T[k*F_ + f];
        float cB = g_c1T[(128 + k)*F_ + f];
        #pragma unroll
        for (int r = 0; r < RB; r++) {
            float hk = hln[r][k];
            ae[r] += ea*hk; be[r] += eB*hk; ac[r] += ca*hk; bc[r] += cB*hk;
        }
    }
    #pragma unroll
    for (int r = 0; r < RB; r++) {
        g_Ae[(row0+r)*F_+f] = ae[r]; g_Be[(row0+r)*F_+f] = be[r];
        g_Ac[(row0+r)*F_+f] = ac[r]; g_Bc[(row0+r)*F_+f] = bc[r];
    }
}

// ---------------- the pair kernel: one CTA per (b,i), 512 threads ----------------
// SMEM floats: w2e 16384 | w2c 16384 | m1eT 128*68 | m1cT 128*68 | dsq 256 | r0 256
//              shift 768 | xi 8 | aggred 8*128 | csum 8*4  = 52520 floats = 210080 B
#define PAIR_SMEM_BYTES (52520 * 4)

__global__ __launch_bounds__(512, 1)
void pair_k(const float* __restrict__ x,   const float* __restrict__ x0,
            const float* __restrict__ e1w, const float* __restrict__ c1w,
            const float* __restrict__ e2b, const float* __restrict__ c2b,
            const float* __restrict__ eiw, const float* __restrict__ eib,
            const float* __restrict__ c3w, const float* __restrict__ c3b,
            float* __restrict__ out_x) {
    extern __shared__ float sm[];
    float* w2e      = sm;                  // [128][128] k-major
    float* w2c      = w2e + F_*F_;
    float* m1eT     = w2c + F_*F_;         // [128 k][68] (j in columns)
    float* m1cT     = m1eT + F_*MS;
    float* dsq_sh   = m1cT + F_*MS;        // [N_]
    float* r0_sh    = dsq_sh + N_;         // [N_]
    float* shift_sh = r0_sh + N_;          // [N_][3]
    float* xi_sh    = shift_sh + N_*3;     // x_i (3) at [0..2], x0_i (3) at [4..6]
    float* aggred   = xi_sh + 8;           // [8][128]
    float* csum_sh  = aggred + 8*F_;       // [8][4]

    int tid  = threadIdx.x;
    int rowI = blockIdx.x;
    int b    = rowI >> 8;
    int i    = rowI & 255;

    // stage both transposed weight matrices into SMEM
    for (int idx = tid; idx < F_*F_/4; idx += 512) {
        ((float4*)w2e)[idx] = ((const float4*)g_w2eT)[idx];
        ((float4*)w2c)[idx] = ((const float4*)g_w2cT)[idx];
    }

    // ---- phase 0 (hoisted): all N_ per-j geometric scalars, once ----
    if (tid < N_) {
        int j = tid;
        float xi0 = x[rowI*3+0], xi1 = x[rowI*3+1], xi2 = x[rowI*3+2];
        const float* xj = x + (b*N_ + j)*3;
        float dx = xi0 - xj[0];
        float dy = xi1 - xj[1];
        float dz = xi2 - xj[2];
        float ds = dx*dx + dy*dy + dz*dz;
        float r  = sqrtf(ds);
        float ri = __fdividef(1.f, r + 1.f);
        dsq_sh[j] = ds;
        shift_sh[j*3+0] = dx * ri;
        shift_sh[j*3+1] = dy * ri;
        shift_sh[j*3+2] = dz * ri;
        float yi0 = x0[rowI*3+0], yi1 = x0[rowI*3+1], yi2 = x0[rowI*3+2];
        const float* x0j = x0 + (b*N_ + j)*3;
        float ex = yi0 - x0j[0];
        float ey = yi1 - x0j[1];
        float ez = yi2 - x0j[2];
        r0_sh[j] = sqrtf(ex*ex + ey*ey + ez*ez);
    }

    // phase-1 mapping: thread handles feature f1, j's congruent to jg (mod 4)
    int f1 = tid >> 2;
    int jg = tid & 3;
    float ae  = g_Ae[rowI*F_ + f1];
    float ac  = g_Ac[rowI*F_ + f1];
    float wed = e1w[f1*258 + 256], wer = e1w[f1*258 + 257];
    float wcd = c1w[f1*258 + 256], wcr = c1w[f1*258 + 257];

    // GEMM mapping: 16 warps; wg = role (0 edge, 1 cor); wj = j-octet; lane tf = f quad
    int w  = tid >> 5, tf = tid & 31;
    int wg = w >> 3, wj = w & 7;
    const float* w2  = wg ? w2c : w2e;
    const float* m1T = wg ? m1cT : m1eT;
    float4 b2   = ((const float4*)(wg ? c2b : e2b))[tf];
    float4 wout = ((const float4*)(wg ? c3w : eiw))[tf];
    float  bout = wg ? c3b[0] : eib[0];

    float4 aggr = make_float4(0.f, 0.f, 0.f, 0.f);   // edge warps only
    float  csum_acc = 0.f;                            // cor warps only

    // ---- preload tile-0 layer-1 inputs into registers ----
    float be_reg[16], bc_reg[16];
    #pragma unroll
    for (int u = 0; u < 16; u++) {
        int j = jg + u*4;
        be_reg[u] = g_Be[(b*N_ + j)*F_ + f1];
        bc_reg[u] = g_Bc[(b*N_ + j)*F_ + f1];
    }

    __syncthreads();

    for (int t = 0; t < N_/TJ; t++) {
        int j0 = t * TJ;

        // ---- phase 1: layer-1 (decomposed) + silu -> transposed m1 tiles ----
        #pragma unroll
        for (int u = 0; u < 16; u++) {
            int jj = jg + u*4;
            float ds = dsq_sh[j0 + jj], rr = r0_sh[j0 + jj];
            float ze = ae + be_reg[u] + wed*ds + wer*rr;
            float zc = ac + bc_reg[u] + wcd*ds + wcr*rr;
            m1eT[f1*MS + jj] = siluf(ze);
            m1cT[f1*MS + jj] = siluf(zc);
        }
        // ---- preload next tile's inputs (drains under the GEMM) ----
        if (t < N_/TJ - 1) {
            #pragma unroll
            for (int u = 0; u < 16; u++) {
                int j = j0 + TJ + jg + u*4;
                be_reg[u] = g_Be[(b*N_ + j)*F_ + f1];
                bc_reg[u] = g_Bc[(b*N_ + j)*F_ + f1];
            }
        }
        __syncthreads();

        // ---- phase 2: role-split GEMM (each warp: 8 j x 128 f, lane: 8 j x 4 f) ----
        {
            unsigned long long acc[4][4];   // [j-pair][f]
            #pragma unroll
            for (int p = 0; p < 4; p++) {
                acc[p][0] = pack2(b2.x, b2.x);
                acc[p][1] = pack2(b2.y, b2.y);
                acc[p][2] = pack2(b2.z, b2.z);
                acc[p][3] = pack2(b2.w, b2.w);
            }
            #pragma unroll 4
            for (int k = 0; k < F_; k++) {
                float4 w4 = *(const float4*)&w2[k*F_ + tf*4];
                ulonglong2 mA = *(const ulonglong2*)&m1T[k*MS + wj*8];      // (j0,j1),(j2,j3)
                ulonglong2 mB = *(const ulonglong2*)&m1T[k*MS + wj*8 + 4];  // (j4,j5),(j6,j7)
                unsigned long long ws;
                ws = pack2(w4.x, w4.x);
                fma2(acc[0][0], mA.x, ws); fma2(acc[1][0], mA.y, ws);
                fma2(acc[2][0], mB.x, ws); fma2(acc[3][0], mB.y, ws);
                ws = pack2(w4.y, w4.y);
                fma2(acc[0][1], mA.x, ws); fma2(acc[1][1], mA.y, ws);
                fma2(acc[2][1], mB.x, ws); fma2(acc[3][1], mB.y, ws);
                ws = pack2(w4.z, w4.z);
                fma2(acc[0][2], mA.x, ws); fma2(acc[1][2], mA.y, ws);
                fma2(acc[2][2], mB.x, ws); fma2(acc[3][2], mB.y, ws);
                ws = pack2(w4.w, w4.w);
                fma2(acc[0][3], mA.x, ws); fma2(acc[1][3], mA.y, ws);
                fma2(acc[2][3], mB.x, ws); fma2(acc[3][3], mB.y, ws);
            }
            // epilogue: per j, silu -> 1-wide head -> gate/accumulate
            #pragma unroll
            for (int p = 0; p < 4; p++) {
                float2 h0 = unpack2(acc[p][0]);
                float2 h1 = unpack2(acc[p][1]);
                float2 h2 = unpack2(acc[p][2]);
                float2 h3 = unpack2(acc[p][3]);
                #pragma unroll
                for (int q = 0; q < 2; q++) {
                    int jj = wj*8 + p*2 + q;
                    float m0 = siluf(q ? h0.y : h0.x);
                    float m1 = siluf(q ? h1.y : h1.x);
                    float m2 = siluf(q ? h2.y : h2.x);
                    float m3 = siluf(q ? h3.y : h3.x);
                    float pdot = m0*wout.x + m1*wout.y + m2*wout.z + m3*wout.w;
                    #pragma unroll
                    for (int o = 16; o; o >>= 1)
                        pdot += __shfl_xor_sync(0xffffffffu, pdot, o);
                    if (wg == 0) {
                        float e = __fdividef(1.f, 1.f + __expf(-(pdot + bout)));
                        if (j0 + jj == i) e = 0.f;          // (1 - eye) mask
                        aggr.x += e*m0; aggr.y += e*m1; aggr.z += e*m2; aggr.w += e*m3;
                    } else {
                        float cw = pdot + bout;              // no activation on cor3
                        float sv = (tf < 3) ? shift_sh[(j0 + jj)*3 + tf] : 0.f;
                        csum_acc += cw * sv;                 // diagonal: shift == 0 exactly
                    }
                }
            }
        }
        __syncthreads();   // protect m1 before next tile overwrites
    }

    // ---- final reductions across warps ----
    if (wg == 0) *((float4*)&aggred[wj*F_ + tf*4]) = aggr;
    else if (tf < 3) csum_sh[wj*4 + tf] = csum_acc;
    __syncthreads();
    if (tid < F_) {
        float s = 0.f;
        #pragma unroll
        for (int ww = 0; ww < 8; ww++) s += aggred[ww*F_ + tid];
        g_agg[rowI*F_ + tid] = s;
    }
    if (tid < 3) {
        float s = 0.f;
        #pragma unroll
        for (int ww = 0; ww < 8; ww++) s += csum_sh[ww*4 + tid];
        out_x[rowI*3 + tid] = g_xln[rowI*3 + tid] + s;
    }
}

// ---------------- kernel: node update, RB rows per CTA ----------------
__global__ void node_k(const float* __restrict__ n1b, const float* __restrict__ n2b,
                       float* __restrict__ out_h) {
    int row0 = blockIdx.x * RB;
    int f    = threadIdx.x;
    __shared__ float hln[RB][F_], agg[RB][F_], nu[RB][F_];
    #pragma unroll
    for (int r = 0; r < RB; r++) {
        hln[r][f] = g_hln[(row0+r)*F_ + f];
        agg[r][f] = g_agg[(row0+r)*F_ + f];
    }
    __syncthreads();
    float z[RB];
    float b1 = n1b[f];
    #pragma unroll
    for (int r = 0; r < RB; r++) z[r] = b1;
    #pragma unroll 4
    for (int k = 0; k < F_; k++) {
        float w1 = g_n1wT[k*F_ + f];
        float w2 = g_n1wT[(128 + k)*F_ + f];
        #pragma unroll
        for (int r = 0; r < RB; r++) z[r] += w1*hln[r][k] + w2*agg[r][k];
    }
    #pragma unroll
    for (int r = 0; r < RB; r++) nu[r][f] = siluf(z[r]);
    __syncthreads();
    float o[RB];
    float b2 = n2b[f];
    #pragma unroll
    for (int r = 0; r < RB; r++) o[r] = b2;
    #pragma unroll 4
    for (int k = 0; k < F_; k++) {
        float wv = g_n2wT[k*F_ + f];
        #pragma unroll
        for (int r = 0; r < RB; r++) o[r] += wv*nu[r][k];
    }
    #pragma unroll
    for (int r = 0; r < RB; r++) out_h[(row0+r)*F_ + f] = hln[r][f] + o[r];
}

// ---------------- launch ----------------
extern "C" void kernel_launch(void* const* d_in, const int* in_sizes, int n_in,
                              void* d_out, int out_size) {
    const float* x      = (const float*)d_in[0];
    const float* h      = (const float*)d_in[1];
    const float* x0     = (const float*)d_in[2];
    const float* lnh_w  = (const float*)d_in[3];
    const float* lnh_b  = (const float*)d_in[4];
    const float* lnx_w  = (const float*)d_in[5];
    const float* lnx_b  = (const float*)d_in[6];
    const float* edg1_w = (const float*)d_in[7];
    const float* edg1_b = (const float*)d_in[8];
    const float* edg2_w = (const float*)d_in[9];
    const float* edg2_b = (const float*)d_in[10];
    const float* edgi_w = (const float*)d_in[11];
    const float* edgi_b = (const float*)d_in[12];
    const float* node1_w = (const float*)d_in[13];
    const float* node1_b = (const float*)d_in[14];
    const float* node2_w = (const float*)d_in[15];
    const float* node2_b = (const float*)d_in[16];
    const float* cor1_w = (const float*)d_in[17];
    const float* cor1_b = (const float*)d_in[18];
    const float* cor2_w = (const float*)d_in[19];
    const float* cor2_b = (const float*)d_in[20];
    const float* cor3_w = (const float*)d_in[21];
    const float* cor3_b = (const float*)d_in[22];

    float* out   = (float*)d_out;
    float* out_x = out;                 // (B,N,3) first
    float* out_h = out + BN_*3;         // then (B,N,F)

    cudaFuncSetAttribute(pair_k, cudaFuncAttributeMaxDynamicSharedMemorySize,
                         PAIR_SMEM_BYTES);

    transpose_k<<<256, F_>>>(edg2_w, cor2_w, node1_w, node2_w, edg1_w, cor1_w);
    pre_k<<<BN_/RB, F_>>>(x, h, lnh_w, lnh_b, lnx_w, lnx_b, edg1_b, cor1_b);
    pair_k<<<BN_, 512, PAIR_SMEM_BYTES>>>(x, x0, edg1_w, cor1_w,
                                          edg2_b, cor2_b, edgi_w, edgi_b,
                                          cor3_w, cor3_b, out_x);
    node_k<<<BN_/RB, F_>>>(node1_b, node2_b, out_h);
}

// round 14
// speedup vs baseline: 1.0456x; 1.0422x over previous
#include <cuda_runtime.h>

// Problem constants (B=4, N=256, F=128)
#define B_  4
#define N_  256
#define F_  128
#define BN_ (B_*N_)
#define TJ  64
#define MS  68        // m1T row stride (floats): stores land conflict-free, 16B aligned
#define RB  2         // rows per CTA in pre_k (512 CTAs -> good occupancy)

// ---------------- device scratch (static: no allocation allowed) ----------------
__device__ float g_hln[BN_*F_];   // layernormed h
__device__ float g_xln[BN_*3];    // layernormed x
__device__ float g_Ae[BN_*F_];    // edg1_w[:, :F] @ h_ln + edg1_b
__device__ float g_Be[BN_*F_];    // edg1_w[:, F:2F] @ h_ln
__device__ float g_Ac[BN_*F_];    // cor1 analogues
__device__ float g_Bc[BN_*F_];
__device__ float g_w2eT[F_*F_];   // edg2_w transposed (k-major)
__device__ float g_w2cT[F_*F_];   // cor2_w transposed
__device__ float g_n1wT[256*F_];  // node1_w transposed (k-major, k=0..255)
__device__ float g_n2wT[F_*F_];   // node2_w transposed
__device__ float g_e1T[256*F_];   // edg1_w[:, :2F] transposed
__device__ float g_c1T[256*F_];   // cor1_w[:, :2F] transposed

__device__ __forceinline__ float siluf(float z) {
    return __fdividef(z, 1.f + __expf(-z));
}

// ---- packed fp32x2 FMA (FFMA2; ptxas never emits it from C++) ----
__device__ __forceinline__ unsigned long long pack2(float x, float y) {
    unsigned long long r;
    asm("mov.b64 %0, {%1, %2};" : "=l"(r) : "f"(x), "f"(y));
    return r;
}
__device__ __forceinline__ void fma2(unsigned long long &d,
                                     unsigned long long a, unsigned long long b) {
    asm("fma.rn.f32x2 %0, %1, %2, %0;" : "+l"(d) : "l"(a), "l"(b));
}
__device__ __forceinline__ float2 unpack2(unsigned long long v) {
    float lo, hi;
    asm("mov.b64 {%0, %1}, %2;" : "=f"(lo), "=f"(hi) : "l"(v));
    return make_float2(lo, hi);
}

// ---------------- kernel: transpose weights to k-major ----------------
__global__ void transpose_k(const float* __restrict__ e2, const float* __restrict__ c2,
                            const float* __restrict__ n1, const float* __restrict__ n2,
                            const float* __restrict__ e1, const float* __restrict__ c1) {
    int k = blockIdx.x;   // 0..255
    int f = threadIdx.x;  // 0..127
    g_n1wT[k*F_ + f] = n1[f*256 + k];
    g_e1T [k*F_ + f] = e1[f*258 + k];
    g_c1T [k*F_ + f] = c1[f*258 + k];
    if (k < F_) {
        g_w2eT[k*F_ + f] = e2[f*F_ + k];
        g_w2cT[k*F_ + f] = c2[f*F_ + k];
        g_n2wT[k*F_ + f] = n2[f*F_ + k];
    }
}

// ---------------- kernel: per-node precompute, RB rows per CTA, 256 threads ----------------
// 256 threads: f = tid&127, half = tid>>7 handles k in [half*64, half*64+64).
__global__ void pre_k(const float* __restrict__ x,  const float* __restrict__ h,
                      const float* __restrict__ lnh_w, const float* __restrict__ lnh_b,
                      const float* __restrict__ lnx_w, const float* __restrict__ lnx_b,
                      const float* __restrict__ e1b, const float* __restrict__ c1b) {
    int row0 = blockIdx.x * RB;
    int tid  = threadIdx.x;          // 0..255
    int f    = tid & 127;
    int half = tid >> 7;
    int lane = tid & 31;
    int wp   = (tid >> 5) & 3;       // == f>>5 for both halves
    __shared__ float hln[RB][F_];
    __shared__ float red[RB][4];
    __shared__ float ps[2][4*RB][F_];  // [half][quantity*RB][f]

    // --- layernorm of h (both halves duplicate the work; writes are identical) ---
    float v[RB], d[RB];
    #pragma unroll
    for (int r = 0; r < RB; r++) v[r] = h[(row0 + r)*F_ + f];
    #pragma unroll
    for (int r = 0; r < RB; r++) {
        float s = v[r];
        #pragma unroll
        for (int o = 16; o; o >>= 1) s += __shfl_xor_sync(0xffffffffu, s, o);
        if (lane == 0) red[r][wp] = s;
    }
    __syncthreads();
    #pragma unroll
    for (int r = 0; r < RB; r++) {
        float mean = (red[r][0] + red[r][1] + red[r][2] + red[r][3]) * (1.f / F_);
        d[r] = v[r] - mean;
    }
    __syncthreads();
    #pragma unroll
    for (int r = 0; r < RB; r++) {
        float s2 = d[r] * d[r];
        #pragma unroll
        for (int o = 16; o; o >>= 1) s2 += __shfl_xor_sync(0xffffffffu, s2, o);
        if (lane == 0) red[r][wp] = s2;
    }
    __syncthreads();
    float gw = lnh_w[f], gb = lnh_b[f];
    #pragma unroll
    for (int r = 0; r < RB; r++) {
        float var  = (red[r][0] + red[r][1] + red[r][2] + red[r][3]) * (1.f / F_);
        float hl = d[r] * rsqrtf(var + 1e-5f) * gw + gb;
        hln[r][f] = hl;
        if (half == 0) g_hln[(row0 + r)*F_ + f] = hl;
    }

    if (tid < RB) {  // layernorm of x (3 comps) for row tid
        int row = row0 + tid;
        float a0 = x[row*3+0], a1 = x[row*3+1], a2 = x[row*3+2];
        float m  = (a0 + a1 + a2) * (1.f/3.f);
        float d0 = a0 - m, d1 = a1 - m, d2 = a2 - m;
        float vr = (d0*d0 + d1*d1 + d2*d2) * (1.f/3.f);
        float rs = rsqrtf(vr + 1e-5f);
        g_xln[row*3+0] = d0*rs*lnx_w[0] + lnx_b[0];
        g_xln[row*3+1] = d1*rs*lnx_w[1] + lnx_b[1];
        g_xln[row*3+2] = d2*rs*lnx_w[2] + lnx_b[2];
    }
    __syncthreads();

    // --- A/B decomposition of layer-1, k split in halves for 2x MLP ---
    float ae[RB], be[RB], ac[RB], bc[RB];
    #pragma unroll
    for (int r = 0; r < RB; r++) { ae[r] = 0.f; be[r] = 0.f; ac[r] = 0.f; bc[r] = 0.f; }
    int k0 = half * 64;
    #pragma unroll 8
    for (int u = 0; u < 64; u++) {
        int k = k0 + u;
        float ea = g_e1T[k*F_ + f];
        float eB = g_e1T[(128 + k)*F_ + f];
        float ca = g_c1T[k*F_ + f];
        float cB = g_c1T[(128 + k)*F_ + f];
        #pragma unroll
        for (int r = 0; r < RB; r++) {
            float hk = hln[r][k];
            ae[r] += ea*hk; be[r] += eB*hk; ac[r] += ca*hk; bc[r] += cB*hk;
        }
    }
    #pragma unroll
    for (int r = 0; r < RB; r++) {
        ps[half][r*4+0][f] = ae[r];
        ps[half][r*4+1][f] = be[r];
        ps[half][r*4+2][f] = ac[r];
        ps[half][r*4+3][f] = bc[r];
    }
    __syncthreads();
    if (half == 0) {
        float eb = e1b[f], cb = c1b[f];
        #pragma unroll
        for (int r = 0; r < RB; r++) {
            g_Ae[(row0+r)*F_+f] = eb + ps[0][r*4+0][f] + ps[1][r*4+0][f];
            g_Be[(row0+r)*F_+f] =      ps[0][r*4+1][f] + ps[1][r*4+1][f];
            g_Ac[(row0+r)*F_+f] = cb + ps[0][r*4+2][f] + ps[1][r*4+2][f];
            g_Bc[(row0+r)*F_+f] =      ps[0][r*4+3][f] + ps[1][r*4+3][f];
        }
    }
}

// ---------------- the pair kernel: one CTA per (b,i), 512 threads ----------------
// SMEM floats: w2e 16384 | w2c 16384 | m1eT 128*68 | m1cT 128*68 | dsq 256 | r0 256
//              shift 768 | xi 8 | aggred 8*128 | csum 8*4 | hln 128 | agg 128 | nu 128
//              = 52904 floats = 211616 B
#define PAIR_SMEM_BYTES (52904 * 4)

__global__ __launch_bounds__(512, 1)
void pair_k(const float* __restrict__ x,   const float* __restrict__ x0,
            const float* __restrict__ e1w, const float* __restrict__ c1w,
            const float* __restrict__ e2b, const float* __restrict__ c2b,
            const float* __restrict__ eiw, const float* __restrict__ eib,
            const float* __restrict__ c3w, const float* __restrict__ c3b,
            const float* __restrict__ n1b, const float* __restrict__ n2b,
            float* __restrict__ out_x, float* __restrict__ out_h) {
    extern __shared__ float sm[];
    float* w2e      = sm;                  // [128][128] k-major
    float* w2c      = w2e + F_*F_;
    float* m1eT     = w2c + F_*F_;         // [128 k][68] (j in columns)
    float* m1cT     = m1eT + F_*MS;
    float* dsq_sh   = m1cT + F_*MS;        // [N_]
    float* r0_sh    = dsq_sh + N_;         // [N_]
    float* shift_sh = r0_sh + N_;          // [N_][3]
    float* xi_sh    = shift_sh + N_*3;     // x_i (3) at [0..2], x0_i (3) at [4..6]
    float* aggred   = xi_sh + 8;           // [8][128], reused as GEMV partials later
    float* csum_sh  = aggred + 8*F_;       // [8][4]
    float* hln_sh   = csum_sh + 8*4;       // [128]
    float* agg_sh   = hln_sh + F_;         // [128]
    float* nu_sh    = agg_sh + F_;         // [128]

    int tid  = threadIdx.x;
    int rowI = blockIdx.x;
    int b    = rowI >> 8;
    int i    = rowI & 255;

    // stage both transposed weight matrices into SMEM
    for (int idx = tid; idx < F_*F_/4; idx += 512) {
        ((float4*)w2e)[idx] = ((const float4*)g_w2eT)[idx];
        ((float4*)w2c)[idx] = ((const float4*)g_w2cT)[idx];
    }
    // stage this row's layernormed h (needed by the fused node update)
    if (tid >= 256 && tid < 256 + F_) hln_sh[tid - 256] = g_hln[rowI*F_ + (tid - 256)];

    // ---- phase 0 (hoisted): all N_ per-j geometric scalars, once ----
    if (tid < N_) {
        int j = tid;
        float xi0 = x[rowI*3+0], xi1 = x[rowI*3+1], xi2 = x[rowI*3+2];
        const float* xj = x + (b*N_ + j)*3;
        float dx = xi0 - xj[0];
        float dy = xi1 - xj[1];
        float dz = xi2 - xj[2];
        float ds = dx*dx + dy*dy + dz*dz;
        float r  = sqrtf(ds);
        float ri = __fdividef(1.f, r + 1.f);
        dsq_sh[j] = ds;
        shift_sh[j*3+0] = dx * ri;
        shift_sh[j*3+1] = dy * ri;
        shift_sh[j*3+2] = dz * ri;
        float yi0 = x0[rowI*3+0], yi1 = x0[rowI*3+1], yi2 = x0[rowI*3+2];
        const float* x0j = x0 + (b*N_ + j)*3;
        float ex = yi0 - x0j[0];
        float ey = yi1 - x0j[1];
        float ez = yi2 - x0j[2];
        r0_sh[j] = sqrtf(ex*ex + ey*ey + ez*ez);
    }

    // phase-1 mapping: thread handles feature f1, j's congruent to jg (mod 4)
    int f1 = tid >> 2;
    int jg = tid & 3;
    float ae  = g_Ae[rowI*F_ + f1];
    float ac  = g_Ac[rowI*F_ + f1];
    float wed = e1w[f1*258 + 256], wer = e1w[f1*258 + 257];
    float wcd = c1w[f1*258 + 256], wcr = c1w[f1*258 + 257];

    // GEMM mapping: 16 warps; wg = role (0 edge, 1 cor); wj = j-octet; lane tf = f quad
    int w  = tid >> 5, tf = tid & 31;
    int wg = w >> 3, wj = w & 7;
    const float* w2  = wg ? w2c : w2e;
    const float* m1T = wg ? m1cT : m1eT;
    float4 b2   = ((const float4*)(wg ? c2b : e2b))[tf];
    float4 wout = ((const float4*)(wg ? c3w : eiw))[tf];
    float  bout = wg ? c3b[0] : eib[0];

    float4 aggr = make_float4(0.f, 0.f, 0.f, 0.f);   // edge warps only
    float  csum_acc = 0.f;                            // cor warps only

    // ---- preload tile-0 layer-1 inputs into registers ----
    float be_reg[16], bc_reg[16];
    #pragma unroll
    for (int u = 0; u < 16; u++) {
        int j = jg + u*4;
        be_reg[u] = g_Be[(b*N_ + j)*F_ + f1];
        bc_reg[u] = g_Bc[(b*N_ + j)*F_ + f1];
    }

    __syncthreads();

    for (int t = 0; t < N_/TJ; t++) {
        int j0 = t * TJ;

        // ---- phase 1: layer-1 (decomposed) + silu -> transposed m1 tiles ----
        #pragma unroll
        for (int u = 0; u < 16; u++) {
            int jj = jg + u*4;
            float ds = dsq_sh[j0 + jj], rr = r0_sh[j0 + jj];
            float ze = ae + be_reg[u] + wed*ds + wer*rr;
            float zc = ac + bc_reg[u] + wcd*ds + wcr*rr;
            m1eT[f1*MS + jj] = siluf(ze);
            m1cT[f1*MS + jj] = siluf(zc);
        }
        // ---- preload next tile's inputs (drains under the GEMM) ----
        if (t < N_/TJ - 1) {
            #pragma unroll
            for (int u = 0; u < 16; u++) {
                int j = j0 + TJ + jg + u*4;
                be_reg[u] = g_Be[(b*N_ + j)*F_ + f1];
                bc_reg[u] = g_Bc[(b*N_ + j)*F_ + f1];
            }
        }
        __syncthreads();

        // ---- phase 2: role-split GEMM (each warp: 8 j x 128 f, lane: 8 j x 4 f) ----
        {
            unsigned long long acc[4][4];   // [j-pair][f]
            #pragma unroll
            for (int p = 0; p < 4; p++) {
                acc[p][0] = pack2(b2.x, b2.x);
                acc[p][1] = pack2(b2.y, b2.y);
                acc[p][2] = pack2(b2.z, b2.z);
                acc[p][3] = pack2(b2.w, b2.w);
            }
            #pragma unroll 4
            for (int k = 0; k < F_; k++) {
                float4 w4 = *(const float4*)&w2[k*F_ + tf*4];
                ulonglong2 mA = *(const ulonglong2*)&m1T[k*MS + wj*8];      // (j0,j1),(j2,j3)
                ulonglong2 mB = *(const ulonglong2*)&m1T[k*MS + wj*8 + 4];  // (j4,j5),(j6,j7)
                unsigned long long ws;
                ws = pack2(w4.x, w4.x);
                fma2(acc[0][0], mA.x, ws); fma2(acc[1][0], mA.y, ws);
                fma2(acc[2][0], mB.x, ws); fma2(acc[3][0], mB.y, ws);
                ws = pack2(w4.y, w4.y);
                fma2(acc[0][1], mA.x, ws); fma2(acc[1][1], mA.y, ws);
                fma2(acc[2][1], mB.x, ws); fma2(acc[3][1], mB.y, ws);
                ws = pack2(w4.z, w4.z);
                fma2(acc[0][2], mA.x, ws); fma2(acc[1][2], mA.y, ws);
                fma2(acc[2][2], mB.x, ws); fma2(acc[3][2], mB.y, ws);
                ws = pack2(w4.w, w4.w);
                fma2(acc[0][3], mA.x, ws); fma2(acc[1][3], mA.y, ws);
                fma2(acc[2][3], mB.x, ws); fma2(acc[3][3], mB.y, ws);
            }
            // epilogue: per j, silu -> 1-wide head -> gate/accumulate
            #pragma unroll
            for (int p = 0; p < 4; p++) {
                float2 h0 = unpack2(acc[p][0]);
                float2 h1 = unpack2(acc[p][1]);
                float2 h2 = unpack2(acc[p][2]);
                float2 h3 = unpack2(acc[p][3]);
                #pragma unroll
                for (int q = 0; q < 2; q++) {
                    int jj = wj*8 + p*2 + q;
                    float m0 = siluf(q ? h0.y : h0.x);
                    float m1 = siluf(q ? h1.y : h1.x);
                    float m2 = siluf(q ? h2.y : h2.x);
                    float m3 = siluf(q ? h3.y : h3.x);
                    float pdot = m0*wout.x + m1*wout.y + m2*wout.z + m3*wout.w;
                    #pragma unroll
                    for (int o = 16; o; o >>= 1)
                        pdot += __shfl_xor_sync(0xffffffffu, pdot, o);
                    if (wg == 0) {
                        float e = __fdividef(1.f, 1.f + __expf(-(pdot + bout)));
                        if (j0 + jj == i) e = 0.f;          // (1 - eye) mask
                        aggr.x += e*m0; aggr.y += e*m1; aggr.z += e*m2; aggr.w += e*m3;
                    } else {
                        float cw = pdot + bout;              // no activation on cor3
                        float sv = (tf < 3) ? shift_sh[(j0 + jj)*3 + tf] : 0.f;
                        csum_acc += cw * sv;                 // diagonal: shift == 0 exactly
                    }
                }
            }
        }
        __syncthreads();   // protect m1 before next tile overwrites
    }

    // ---- reductions across warps: agg (into SMEM) + coordinate output ----
    if (wg == 0) *((float4*)&aggred[wj*F_ + tf*4]) = aggr;
    else if (tf < 3) csum_sh[wj*4 + tf] = csum_acc;
    __syncthreads();
    if (tid < F_) {
        float s = 0.f;
        #pragma unroll
        for (int ww = 0; ww < 8; ww++) s += aggred[ww*F_ + tid];
        agg_sh[tid] = s;
    }
    if (tid < 3) {
        float s = 0.f;
        #pragma unroll
        for (int ww = 0; ww < 8; ww++) s += csum_sh[ww*4 + tid];
        out_x[rowI*3 + tid] = g_xln[rowI*3 + tid] + s;
    }
    __syncthreads();

    // ---- fused node update: 512 threads, k split 4 ways ----
    {
        int f  = tid & 127;
        int kg = tid >> 7;          // 0..3
        int k0 = kg * 32;
        float z = 0.f;
        #pragma unroll 8
        for (int u = 0; u < 32; u++) {
            int k = k0 + u;
            z += g_n1wT[k*F_ + f] * hln_sh[k];
        }
        #pragma unroll 8
        for (int u = 0; u < 32; u++) {
            int k = k0 + u;
            z += g_n1wT[(128 + k)*F_ + f] * agg_sh[k];
        }
        aggred[kg*F_ + f] = z;      // reuse aggred as GEMV partial buffer
        __syncthreads();
        if (tid < F_) {
            float zz = n1b[tid] + aggred[tid] + aggred[F_ + tid]
                                + aggred[2*F_ + tid] + aggred[3*F_ + tid];
            nu_sh[tid] = siluf(zz);
        }
        __syncthreads();
        float o = 0.f;
        #pragma unroll 8
        for (int u = 0; u < 32; u++) {
            int k = k0 + u;
            o += g_n2wT[k*F_ + f] * nu_sh[k];
        }
        aggred[kg*F_ + f] = o;
        __syncthreads();
        if (tid < F_) {
            out_h[rowI*F_ + tid] = hln_sh[tid] + n2b[tid]
                                 + aggred[tid] + aggred[F_ + tid]
                                 + aggred[2*F_ + tid] + aggred[3*F_ + tid];
        }
    }
}

// ---------------- launch ----------------
extern "C" void kernel_launch(void* const* d_in, const int* in_sizes, int n_in,
                              void* d_out, int out_size) {
    const float* x      = (const float*)d_in[0];
    const float* h      = (const float*)d_in[1];
    const float* x0     = (const float*)d_in[2];
    const float* lnh_w  = (const float*)d_in[3];
    const float* lnh_b  = (const float*)d_in[4];
    const float* lnx_w  = (const float*)d_in[5];
    const float* lnx_b  = (const float*)d_in[6];
    const float* edg1_w = (const float*)d_in[7];
    const float* edg1_b = (const float*)d_in[8];
    const float* edg2_w = (const float*)d_in[9];
    const float* edg2_b = (const float*)d_in[10];
    const float* edgi_w = (const float*)d_in[11];
    const float* edgi_b = (const float*)d_in[12];
    const float* node1_w = (const float*)d_in[13];
    const float* node1_b = (const float*)d_in[14];
    const float* node2_w = (const float*)d_in[15];
    const float* node2_b = (const float*)d_in[16];
    const float* cor1_w = (const float*)d_in[17];
    const float* cor1_b = (const float*)d_in[18];
    const float* cor2_w = (const float*)d_in[19];
    const float* cor2_b = (const float*)d_in[20];
    const float* cor3_w = (const float*)d_in[21];
    const float* cor3_b = (const float*)d_in[22];

    float* out   = (float*)d_out;
    float* out_x = out;                 // (B,N,3) first
    float* out_h = out + BN_*3;         // then (B,N,F)

    cudaFuncSetAttribute(pair_k, cudaFuncAttributeMaxDynamicSharedMemorySize,
                         PAIR_SMEM_BYTES);

    transpose_k<<<256, F_>>>(edg2_w, cor2_w, node1_w, node2_w, edg1_w, cor1_w);
    pre_k<<<BN_/RB, 256>>>(x, h, lnh_w, lnh_b, lnx_w, lnx_b, edg1_b, cor1_b);
    pair_k<<<BN_, 512, PAIR_SMEM_BYTES>>>(x, x0, edg1_w, cor1_w,
                                          edg2_b, cor2_b, edgi_w, edgi_b,
                                          cor3_w, cor3_b, node1_b, node2_b,
                                          out_x, out_h);
}

// round 15
// speedup vs baseline: 1.0501x; 1.0043x over previous
#include <cuda_runtime.h>

// Problem constants (B=4, N=256, F=128)
#define B_  4
#define N_  256
#define F_  128
#define BN_ (B_*N_)
#define TJ  64
#define MS  68        // m1T row stride (floats): stores land conflict-free, 16B aligned
#define RB  2         // rows per CTA in pre_k (512 CTAs -> good occupancy)

// ---------------- device scratch (static: no allocation allowed) ----------------
__device__ float g_hln[BN_*F_];   // layernormed h
__device__ float g_xln[BN_*3];    // layernormed x
__device__ float g_Ae[BN_*F_];    // edg1_w[:, :F] @ h_ln + edg1_b
__device__ float g_Be[BN_*F_];    // edg1_w[:, F:2F] @ h_ln
__device__ float g_Ac[BN_*F_];    // cor1 analogues
__device__ float g_Bc[BN_*F_];
__device__ float g_w2eT[F_*F_];   // edg2_w transposed (k-major)
__device__ float g_w2cT[F_*F_];   // cor2_w transposed
__device__ float g_n1wT[256*F_];  // node1_w transposed (k-major, k=0..255)
__device__ float g_n2wT[F_*F_];   // node2_w transposed
__device__ float g_e1T[256*F_];   // edg1_w[:, :2F] transposed
__device__ float g_c1T[256*F_];   // cor1_w[:, :2F] transposed

__device__ __forceinline__ float siluf(float z) {
    return __fdividef(z, 1.f + __expf(-z));
}

// ---- packed fp32x2 FMA (FFMA2; ptxas never emits it from C++) ----
__device__ __forceinline__ unsigned long long pack2(float x, float y) {
    unsigned long long r;
    asm("mov.b64 %0, {%1, %2};" : "=l"(r) : "f"(x), "f"(y));
    return r;
}
__device__ __forceinline__ void fma2(unsigned long long &d,
                                     unsigned long long a, unsigned long long b) {
    asm("fma.rn.f32x2 %0, %1, %2, %0;" : "+l"(d) : "l"(a), "l"(b));
}
__device__ __forceinline__ float2 unpack2(unsigned long long v) {
    float lo, hi;
    asm("mov.b64 {%0, %1}, %2;" : "=f"(lo), "=f"(hi) : "l"(v));
    return make_float2(lo, hi);
}

// ---------------- kernel: transpose weights to k-major ----------------
__global__ void transpose_k(const float* __restrict__ e2, const float* __restrict__ c2,
                            const float* __restrict__ n1, const float* __restrict__ n2,
                            const float* __restrict__ e1, const float* __restrict__ c1) {
    int k = blockIdx.x;   // 0..255
    int f = threadIdx.x;  // 0..127
    g_n1wT[k*F_ + f] = n1[f*256 + k];
    g_e1T [k*F_ + f] = e1[f*258 + k];
    g_c1T [k*F_ + f] = c1[f*258 + k];
    if (k < F_) {
        g_w2eT[k*F_ + f] = e2[f*F_ + k];
        g_w2cT[k*F_ + f] = c2[f*F_ + k];
        g_n2wT[k*F_ + f] = n2[f*F_ + k];
    }
}

// ---------------- kernel: per-node precompute, RB rows per CTA, 256 threads ----------------
// 256 threads: f = tid&127, half = tid>>7 handles k in [half*64, half*64+64).
__global__ void pre_k(const float* __restrict__ x,  const float* __restrict__ h,
                      const float* __restrict__ lnh_w, const float* __restrict__ lnh_b,
                      const float* __restrict__ lnx_w, const float* __restrict__ lnx_b,
                      const float* __restrict__ e1b, const float* __restrict__ c1b) {
    int row0 = blockIdx.x * RB;
    int tid  = threadIdx.x;          // 0..255
    int f    = tid & 127;
    int half = tid >> 7;
    int lane = tid & 31;
    int wp   = (tid >> 5) & 3;       // == f>>5 for both halves
    __shared__ float hln[RB][F_];
    __shared__ float red[RB][4];
    __shared__ float ps[2][4*RB][F_];  // [half][quantity*RB][f]

    // --- layernorm of h (both halves duplicate the work; writes are identical) ---
    float v[RB], d[RB];
    #pragma unroll
    for (int r = 0; r < RB; r++) v[r] = h[(row0 + r)*F_ + f];
    #pragma unroll
    for (int r = 0; r < RB; r++) {
        float s = v[r];
        #pragma unroll
        for (int o = 16; o; o >>= 1) s += __shfl_xor_sync(0xffffffffu, s, o);
        if (lane == 0) red[r][wp] = s;
    }
    __syncthreads();
    #pragma unroll
    for (int r = 0; r < RB; r++) {
        float mean = (red[r][0] + red[r][1] + red[r][2] + red[r][3]) * (1.f / F_);
        d[r] = v[r] - mean;
    }
    __syncthreads();
    #pragma unroll
    for (int r = 0; r < RB; r++) {
        float s2 = d[r] * d[r];
        #pragma unroll
        for (int o = 16; o; o >>= 1) s2 += __shfl_xor_sync(0xffffffffu, s2, o);
        if (lane == 0) red[r][wp] = s2;
    }
    __syncthreads();
    float gw = lnh_w[f], gb = lnh_b[f];
    #pragma unroll
    for (int r = 0; r < RB; r++) {
        float var  = (red[r][0] + red[r][1] + red[r][2] + red[r][3]) * (1.f / F_);
        float hl = d[r] * rsqrtf(var + 1e-5f) * gw + gb;
        hln[r][f] = hl;
        if (half == 0) g_hln[(row0 + r)*F_ + f] = hl;
    }

    if (tid < RB) {  // layernorm of x (3 comps) for row tid
        int row = row0 + tid;
        float a0 = x[row*3+0], a1 = x[row*3+1], a2 = x[row*3+2];
        float m  = (a0 + a1 + a2) * (1.f/3.f);
        float d0 = a0 - m, d1 = a1 - m, d2 = a2 - m;
        float vr = (d0*d0 + d1*d1 + d2*d2) * (1.f/3.f);
        float rs = rsqrtf(vr + 1e-5f);
        g_xln[row*3+0] = d0*rs*lnx_w[0] + lnx_b[0];
        g_xln[row*3+1] = d1*rs*lnx_w[1] + lnx_b[1];
        g_xln[row*3+2] = d2*rs*lnx_w[2] + lnx_b[2];
    }
    __syncthreads();

    // --- A/B decomposition of layer-1, k split in halves for 2x MLP ---
    float ae[RB], be[RB], ac[RB], bc[RB];
    #pragma unroll
    for (int r = 0; r < RB; r++) { ae[r] = 0.f; be[r] = 0.f; ac[r] = 0.f; bc[r] = 0.f; }
    int k0 = half * 64;
    #pragma unroll 8
    for (int u = 0; u < 64; u++) {
        int k = k0 + u;
        float ea = g_e1T[k*F_ + f];
        float eB = g_e1T[(128 + k)*F_ + f];
        float ca = g_c1T[k*F_ + f];
        float cB = g_c1T[(128 + k)*F_ + f];
        #pragma unroll
        for (int r = 0; r < RB; r++) {
            float hk = hln[r][k];
            ae[r] += ea*hk; be[r] += eB*hk; ac[r] += ca*hk; bc[r] += cB*hk;
        }
    }
    #pragma unroll
    for (int r = 0; r < RB; r++) {
        ps[half][r*4+0][f] = ae[r];
        ps[half][r*4+1][f] = be[r];
        ps[half][r*4+2][f] = ac[r];
        ps[half][r*4+3][f] = bc[r];
    }
    __syncthreads();
    if (half == 0) {
        float eb = e1b[f], cb = c1b[f];
        #pragma unroll
        for (int r = 0; r < RB; r++) {
            g_Ae[(row0+r)*F_+f] = eb + ps[0][r*4+0][f] + ps[1][r*4+0][f];
            g_Be[(row0+r)*F_+f] =      ps[0][r*4+1][f] + ps[1][r*4+1][f];
            g_Ac[(row0+r)*F_+f] = cb + ps[0][r*4+2][f] + ps[1][r*4+2][f];
            g_Bc[(row0+r)*F_+f] =      ps[0][r*4+3][f] + ps[1][r*4+3][f];
        }
    }
}

// ---------------- the pair kernel: one CTA per (b,i), 512 threads ----------------
// SMEM floats: w2e 16384 | w2c 16384 | m1eT 128*68 | m1cT 128*68 | dsq 256 | r0 256
//              shift 768 | xi 8 | aggred 8*128 | csum 8*4 | hln 128 | agg 128 | nu 128
//              = 52904 floats = 211616 B
#define PAIR_SMEM_BYTES (52904 * 4)

__global__ __launch_bounds__(512, 1)
void pair_k(const float* __restrict__ x,   const float* __restrict__ x0,
            const float* __restrict__ e1w, const float* __restrict__ c1w,
            const float* __restrict__ e2b, const float* __restrict__ c2b,
            const float* __restrict__ eiw, const float* __restrict__ eib,
            const float* __restrict__ c3w, const float* __restrict__ c3b,
            const float* __restrict__ n1b, const float* __restrict__ n2b,
            float* __restrict__ out_x, float* __restrict__ out_h) {
    extern __shared__ float sm[];
    float* w2e      = sm;                  // [128][128] k-major
    float* w2c      = w2e + F_*F_;
    float* m1eT     = w2c + F_*F_;         // [128 k][68] (j in columns)
    float* m1cT     = m1eT + F_*MS;
    float* dsq_sh   = m1cT + F_*MS;        // [N_]
    float* r0_sh    = dsq_sh + N_;         // [N_]
    float* shift_sh = r0_sh + N_;          // [N_][3]
    float* xi_sh    = shift_sh + N_*3;     // x_i (3) at [0..2], x0_i (3) at [4..6]
    float* aggred   = xi_sh + 8;           // [8][128], reused as GEMV partials later
    float* csum_sh  = aggred + 8*F_;       // [8][4]
    float* hln_sh   = csum_sh + 8*4;       // [128]
    float* agg_sh   = hln_sh + F_;         // [128]
    float* nu_sh    = agg_sh + F_;         // [128]

    int tid  = threadIdx.x;
    int rowI = blockIdx.x;
    int b    = rowI >> 8;
    int i    = rowI & 255;

    // stage both transposed weight matrices into SMEM
    for (int idx = tid; idx < F_*F_/4; idx += 512) {
        ((float4*)w2e)[idx] = ((const float4*)g_w2eT)[idx];
        ((float4*)w2c)[idx] = ((const float4*)g_w2cT)[idx];
    }
    // stage this row's layernormed h (needed by the fused node update)
    if (tid >= 256 && tid < 256 + F_) hln_sh[tid - 256] = g_hln[rowI*F_ + (tid - 256)];

    // ---- phase 0 (hoisted): all N_ per-j geometric scalars, once ----
    if (tid < N_) {
        int j = tid;
        float xi0 = x[rowI*3+0], xi1 = x[rowI*3+1], xi2 = x[rowI*3+2];
        const float* xj = x + (b*N_ + j)*3;
        float dx = xi0 - xj[0];
        float dy = xi1 - xj[1];
        float dz = xi2 - xj[2];
        float ds = dx*dx + dy*dy + dz*dz;
        float r  = sqrtf(ds);
        float ri = __fdividef(1.f, r + 1.f);
        dsq_sh[j] = ds;
        shift_sh[j*3+0] = dx * ri;
        shift_sh[j*3+1] = dy * ri;
        shift_sh[j*3+2] = dz * ri;
        float yi0 = x0[rowI*3+0], yi1 = x0[rowI*3+1], yi2 = x0[rowI*3+2];
        const float* x0j = x0 + (b*N_ + j)*3;
        float ex = yi0 - x0j[0];
        float ey = yi1 - x0j[1];
        float ez = yi2 - x0j[2];
        r0_sh[j] = sqrtf(ex*ex + ey*ey + ez*ez);
    }

    // phase-1 mapping: thread handles feature f1, j's congruent to jg (mod 4)
    int f1 = tid >> 2;
    int jg = tid & 3;
    float ae  = g_Ae[rowI*F_ + f1];
    float ac  = g_Ac[rowI*F_ + f1];
    float wed = e1w[f1*258 + 256], wer = e1w[f1*258 + 257];
    float wcd = c1w[f1*258 + 256], wcr = c1w[f1*258 + 257];

    // GEMM mapping: 16 warps; wg = role (0 edge, 1 cor); wj = j-octet; lane tf = f quad
    int w  = tid >> 5, tf = tid & 31;
    int wg = w >> 3, wj = w & 7;
    const float* w2  = wg ? w2c : w2e;
    const float* m1T = wg ? m1cT : m1eT;
    float4 b2   = ((const float4*)(wg ? c2b : e2b))[tf];
    float4 wout = ((const float4*)(wg ? c3w : eiw))[tf];
    float  bout = wg ? c3b[0] : eib[0];

    float4 aggr = make_float4(0.f, 0.f, 0.f, 0.f);   // edge warps only
    float  csum_acc = 0.f;                            // cor warps only

    // ---- preload tile-0 layer-1 inputs into registers ----
    float be_reg[16], bc_reg[16];
    #pragma unroll
    for (int u = 0; u < 16; u++) {
        int j = jg + u*4;
        be_reg[u] = g_Be[(b*N_ + j)*F_ + f1];
        bc_reg[u] = g_Bc[(b*N_ + j)*F_ + f1];
    }

    __syncthreads();

    for (int t = 0; t < N_/TJ; t++) {
        int j0 = t * TJ;

        // ---- phase 1: layer-1 (decomposed) + silu -> transposed m1 tiles ----
        #pragma unroll
        for (int u = 0; u < 16; u++) {
            int jj = jg + u*4;
            float ds = dsq_sh[j0 + jj], rr = r0_sh[j0 + jj];
            float ze = ae + be_reg[u] + wed*ds + wer*rr;
            float zc = ac + bc_reg[u] + wcd*ds + wcr*rr;
            m1eT[f1*MS + jj] = siluf(ze);
            m1cT[f1*MS + jj] = siluf(zc);
        }
        // ---- preload next tile's inputs (drains under the GEMM) ----
        if (t < N_/TJ - 1) {
            #pragma unroll
            for (int u = 0; u < 16; u++) {
                int j = j0 + TJ + jg + u*4;
                be_reg[u] = g_Be[(b*N_ + j)*F_ + f1];
                bc_reg[u] = g_Bc[(b*N_ + j)*F_ + f1];
            }
        }
        __syncthreads();

        // ---- phase 2: role-split GEMM (each warp: 8 j x 128 f, lane: 8 j x 4 f) ----
        {
            unsigned long long acc[4][4];   // [j-pair][f]
            #pragma unroll
            for (int p = 0; p < 4; p++) {
                acc[p][0] = pack2(b2.x, b2.x);
                acc[p][1] = pack2(b2.y, b2.y);
                acc[p][2] = pack2(b2.z, b2.z);
                acc[p][3] = pack2(b2.w, b2.w);
            }
            #pragma unroll 4
            for (int k = 0; k < F_; k++) {
                float4 w4 = *(const float4*)&w2[k*F_ + tf*4];
                ulonglong2 mA = *(const ulonglong2*)&m1T[k*MS + wj*8];      // (j0,j1),(j2,j3)
                ulonglong2 mB = *(const ulonglong2*)&m1T[k*MS + wj*8 + 4];  // (j4,j5),(j6,j7)
                unsigned long long ws;
                ws = pack2(w4.x, w4.x);
                fma2(acc[0][0], mA.x, ws); fma2(acc[1][0], mA.y, ws);
                fma2(acc[2][0], mB.x, ws); fma2(acc[3][0], mB.y, ws);
                ws = pack2(w4.y, w4.y);
                fma2(acc[0][1], mA.x, ws); fma2(acc[1][1], mA.y, ws);
                fma2(acc[2][1], mB.x, ws); fma2(acc[3][1], mB.y, ws);
                ws = pack2(w4.z, w4.z);
                fma2(acc[0][2], mA.x, ws); fma2(acc[1][2], mA.y, ws);
                fma2(acc[2][2], mB.x, ws); fma2(acc[3][2], mB.y, ws);
                ws = pack2(w4.w, w4.w);
                fma2(acc[0][3], mA.x, ws); fma2(acc[1][3], mA.y, ws);
                fma2(acc[2][3], mB.x, ws); fma2(acc[3][3], mB.y, ws);
            }
            // epilogue: per j, silu -> 1-wide head -> gate/accumulate
            #pragma unroll
            for (int p = 0; p < 4; p++) {
                float2 h0 = unpack2(acc[p][0]);
                float2 h1 = unpack2(acc[p][1]);
                float2 h2 = unpack2(acc[p][2]);
                float2 h3 = unpack2(acc[p][3]);
                #pragma unroll
                for (int q = 0; q < 2; q++) {
                    int jj = wj*8 + p*2 + q;
                    float m0 = siluf(q ? h0.y : h0.x);
                    float m1 = siluf(q ? h1.y : h1.x);
                    float m2 = siluf(q ? h2.y : h2.x);
                    float m3 = siluf(q ? h3.y : h3.x);
                    float pdot = m0*wout.x + m1*wout.y + m2*wout.z + m3*wout.w;
                    #pragma unroll
                    for (int o = 16; o; o >>= 1)
                        pdot += __shfl_xor_sync(0xffffffffu, pdot, o);
                    if (wg == 0) {
                        float e = __fdividef(1.f, 1.f + __expf(-(pdot + bout)));
                        if (j0 + jj == i) e = 0.f;          // (1 - eye) mask
                        aggr.x += e*m0; aggr.y += e*m1; aggr.z += e*m2; aggr.w += e*m3;
                    } else {
                        float cw = pdot + bout;              // no activation on cor3
                        float sv = (tf < 3) ? shift_sh[(j0 + jj)*3 + tf] : 0.f;
                        csum_acc += cw * sv;                 // diagonal: shift == 0 exactly
                    }
                }
            }
        }
        __syncthreads();   // protect m1 before next tile overwrites
    }

    // ---- reductions across warps: agg (into SMEM) + coordinate output ----
    if (wg == 0) *((float4*)&aggred[wj*F_ + tf*4]) = aggr;
    else if (tf < 3) csum_sh[wj*4 + tf] = csum_acc;
    __syncthreads();
    if (tid < F_) {
        float s = 0.f;
        #pragma unroll
        for (int ww = 0; ww < 8; ww++) s += aggred[ww*F_ + tid];
        agg_sh[tid] = s;
    }
    if (tid < 3) {
        float s = 0.f;
        #pragma unroll
        for (int ww = 0; ww < 8; ww++) s += csum_sh[ww*4 + tid];
        out_x[rowI*3 + tid] = g_xln[rowI*3 + tid] + s;
    }
    __syncthreads();

    // ---- fused node update: 512 threads, k split 4 ways ----
    {
        int f  = tid & 127;
        int kg = tid >> 7;          // 0..3
        int k0 = kg * 32;
        float z = 0.f;
        #pragma unroll 8
        for (int u = 0; u < 32; u++) {
            int k = k0 + u;
            z += g_n1wT[k*F_ + f] * hln_sh[k];
        }
        #pragma unroll 8
        for (int u = 0; u < 32; u++) {
            int k = k0 + u;
            z += g_n1wT[(128 + k)*F_ + f] * agg_sh[k];
        }
        aggred[kg*F_ + f] = z;      // reuse aggred as GEMV partial buffer
        __syncthreads();
        if (tid < F_) {
            float zz = n1b[tid] + aggred[tid] + aggred[F_ + tid]
                                + aggred[2*F_ + tid] + aggred[3*F_ + tid];
            nu_sh[tid] = siluf(zz);
        }
        __syncthreads();
        float o = 0.f;
        #pragma unroll 8
        for (int u = 0; u < 32; u++) {
            int k = k0 + u;
            o += g_n2wT[k*F_ + f] * nu_sh[k];
        }
        aggred[kg*F_ + f] = o;
        __syncthreads();
        if (tid < F_) {
            out_h[rowI*F_ + tid] = hln_sh[tid] + n2b[tid]
                                 + aggred[tid] + aggred[F_ + tid]
                                 + aggred[2*F_ + tid] + aggred[3*F_ + tid];
        }
    }
}

// ---------------- launch ----------------
extern "C" void kernel_launch(void* const* d_in, const int* in_sizes, int n_in,
                              void* d_out, int out_size) {
    const float* x      = (const float*)d_in[0];
    const float* h      = (const float*)d_in[1];
    const float* x0     = (const float*)d_in[2];
    const float* lnh_w  = (const float*)d_in[3];
    const float* lnh_b  = (const float*)d_in[4];
    const float* lnx_w  = (const float*)d_in[5];
    const float* lnx_b  = (const float*)d_in[6];
    const float* edg1_w = (const float*)d_in[7];
    const float* edg1_b = (const float*)d_in[8];
    const float* edg2_w = (const float*)d_in[9];
    const float* edg2_b = (const float*)d_in[10];
    const float* edgi_w = (const float*)d_in[11];
    const float* edgi_b = (const float*)d_in[12];
    const float* node1_w = (const float*)d_in[13];
    const float* node1_b = (const float*)d_in[14];
    const float* node2_w = (const float*)d_in[15];
    const float* node2_b = (const float*)d_in[16];
    const float* cor1_w = (const float*)d_in[17];
    const float* cor1_b = (const float*)d_in[18];
    const float* cor2_w = (const float*)d_in[19];
    const float* cor2_b = (const float*)d_in[20];
    const float* cor3_w = (const float*)d_in[21];
    const float* cor3_b = (const float*)d_in[22];

    float* out   = (float*)d_out;
    float* out_x = out;                 // (B,N,3) first
    float* out_h = out + BN_*3;         // then (B,N,F)

    cudaFuncSetAttribute(pair_k, cudaFuncAttributeMaxDynamicSharedMemorySize,
                         PAIR_SMEM_BYTES);

    transpose_k<<<256, F_>>>(edg2_w, cor2_w, node1_w, node2_w, edg1_w, cor1_w);
    pre_k<<<BN_/RB, 256>>>(x, h, lnh_w, lnh_b, lnx_w, lnx_b, edg1_b, cor1_b);
    pair_k<<<BN_, 512, PAIR_SMEM_BYTES>>>(x, x0, edg1_w, cor1_w,
                                          edg2_b, cor2_b, edgi_w, edgi_b,
                                          cor3_w, cor3_b, node1_b, node2_b,
                                          out_x, out_h);
}